// round 4
// baseline (speedup 1.0000x reference)
#include <cuda_runtime.h>
#include <cstddef>

#define HH 51     // hidden size
#define BT 16     // batch rows per block
#define NT 448    // threads: 112 gate-pair groups x 4 batch-quads
#define TT 512    // timesteps
#define BB 2048   // batch
#define TCH 64    // x staging chunk

// smem floats: sW1 26*112*4 + sWC 51*112*4 + sb1/sb2/swi1 224*3 + sfcw 64
//            + h1d/h2d (52*16 u64 each = 3328 f) + ag 4*56*16 + xs 16*64
#define SW1_F  (26*112*4)
#define SWC_F  (51*112*4)
#define SMEM_FLOATS (SW1_F + SWC_F + 3*224 + 64 + 2*52*16*2 + 4*56*16 + BT*TCH)

typedef unsigned long long u64;

__device__ __forceinline__ u64 pack2(float lo, float hi) {
    u64 r; asm("mov.b64 %0, {%1,%2};" : "=l"(r) : "f"(lo), "f"(hi)); return r;
}
__device__ __forceinline__ void unpack2(u64 v, float& lo, float& hi) {
    asm("mov.b64 {%0,%1}, %2;" : "=f"(lo), "=f"(hi) : "l"(v));
}
__device__ __forceinline__ u64 fma2(u64 a, u64 b, u64 c) {
    u64 d; asm("fma.rn.f32x2 %0, %1, %2, %3;" : "=l"(d) : "l"(a), "l"(b), "l"(c)); return d;
}
// act(v) = a * rcp(1 + ex2(c*v)) + d   (sigmoid: c=-log2e,a=1,d=0 | tanh: c=2log2e,a=-2,d=1)
__device__ __forceinline__ float actf(float v, float c, float a, float d) {
    float e; asm("ex2.approx.ftz.f32 %0, %1;" : "=f"(e) : "f"(v * c));
    float r; asm("rcp.approx.ftz.f32 %0, %1;" : "=f"(r) : "f"(1.f + e));
    return fmaf(a, r, d);
}
#define C_SIG (-1.442695041f)
#define C_TNH ( 2.885390082f)
__device__ __forceinline__ float tanh_c(float v) { return actf(v, C_TNH, -2.f, 1.f); }

__global__ void __launch_bounds__(NT, 1) lstm2_persistent_kernel(
    const float* __restrict__ x,
    const float* __restrict__ Wih1, const float* __restrict__ bih1,
    const float* __restrict__ Whh1, const float* __restrict__ bhh1,
    const float* __restrict__ Wih2, const float* __restrict__ bih2,
    const float* __restrict__ Whh2, const float* __restrict__ bhh2,
    const float* __restrict__ fcwg, const float* __restrict__ fcbg,
    float* __restrict__ out)
{
    extern __shared__ float sm[];
    float* sW1  = sm;                        // [26 k2][112 gp][4]: (g0[k],g1[k],g0[k+1],g1[k+1]) of W_hh1
    float* sWC  = sW1 + SW1_F;               // [51 k][112 gp][4]: (Wih2 g0,g1 , Whh2 g0,g1)
    float* sb1  = sWC + SWC_F;               // [112][2]
    float* sb2  = sb1 + 224;                 // [112][2]
    float* swi1 = sb2 + 224;                 // [112][2]
    float* sfcw = swi1 + 224;                // [64]
    u64*   h1d  = (u64*)(sfcw + 64);         // [52][16] duplicated (h,h); row 51 stays 0
    u64*   h2d  = h1d + 52*16;               // [52][16]
    float* ag   = (float*)(h2d + 52*16);     // [4 class][56 jg][16 b]
    float* xs   = ag + 4*56*16;              // [16][64]

    const int tid = threadIdx.x;
    const int b0  = blockIdx.x * BT;

    // ---------------- one-time weight prep ----------------
    for (int i = tid; i < SW1_F; i += NT) {
        int k2 = i / 448, rem = i % 448;
        int gp_ = rem >> 2, s = rem & 3;
        int k = k2 * 2 + (s >> 1);
        int cls = (gp_ & 1) * 2 + (s & 1);
        int j = gp_ >> 1;
        sW1[i] = (j < HH && k < HH) ? Whh1[(cls*HH + j)*HH + k] : 0.f;
    }
    for (int i = tid; i < SWC_F; i += NT) {
        int k = i / 448, rem = i % 448;
        int gp_ = rem >> 2, s = rem & 3;
        int cls = (gp_ & 1) * 2 + (s & 1);
        int j = gp_ >> 1;
        const float* W = (s < 2) ? Wih2 : Whh2;
        sWC[i] = (j < HH) ? W[(cls*HH + j)*HH + k] : 0.f;
    }
    for (int i = tid; i < 224; i += NT) {
        int gp_ = i >> 1, gi = i & 1;
        int cls = (gp_ & 1) * 2 + gi;
        int j = gp_ >> 1;
        int g = cls * HH + j;
        bool real = (j < HH);
        sb1[i]  = real ? (bih1[g] + bhh1[g]) : 0.f;
        sb2[i]  = real ? (bih2[g] + bhh2[g]) : 0.f;
        swi1[i] = real ? Wih1[g] : 0.f;
    }
    for (int k = tid; k < 64; k += NT) sfcw[k] = (k < HH) ? fcwg[k] : 0.f;
    for (int i = tid; i < 52*16; i += NT) { h1d[i] = 0ull; h2d[i] = 0ull; }
    const float fcb = fcbg[0];

    // lane map: bq fast (wavefront merge), gate-pair group slow
    const int bq = tid & 3;
    const int gp = tid >> 2;          // 0..111
    const int jg = gp >> 1;
    const int half = gp & 1;
    const int bbase = bq * 4;

    __syncthreads();

    const u64 b1p  = *(const u64*)&sb1[gp*2];
    const u64 b2p  = *(const u64*)&sb2[gp*2];
    const u64 wi1p = *(const u64*)&swi1[gp*2];
    // gate g0: half0 -> sigmoid (i), half1 -> tanh (g). gate g1: always sigmoid (f / o).
    const float c0 = half ? C_TNH : C_SIG;
    const float a0 = half ? -2.f : 1.f;
    const float d0 = half ?  1.f : 0.f;
    const int agr0 = (half*2)     * 896 + jg*16 + bbase;  // class row for g0
    const int agr1 = (half*2 + 1) * 896 + jg*16 + bbase;  // class row for g1

    // phase B/D per-thread cell state
    const int jA = tid >> 4, bA = tid & 15;          // idx0 = tid       (j 0..27)
    const int jB = (tid + 448) >> 4, bB = tid & 15;  // idx1 = tid + 448 (j 28..55)
    const bool vB = (tid < 368);                     // j < 51
    float c1a = 0.f, c1b = 0.f, c2a = 0.f, c2b = 0.f;

    for (int t = 0; t < TT; ++t) {
        const int tc = t & (TCH - 1);
        if (tc == 0) {
            for (int i = tid; i < BT*TCH; i += NT) {
                int b = i >> 6, u = i & 63;
                xs[i] = x[(size_t)(b0 + b) * TT + t + u];
            }
            __syncthreads();
        }

        // ======== Phase A: cell-1 gates ========
        u64 acc0, acc1, acc2, acc3;
        {
            float x0 = xs[(bbase + 0)*TCH + tc];
            float x1 = xs[(bbase + 1)*TCH + tc];
            float x2 = xs[(bbase + 2)*TCH + tc];
            float x3 = xs[(bbase + 3)*TCH + tc];
            acc0 = fma2(wi1p, pack2(x0, x0), b1p);
            acc1 = fma2(wi1p, pack2(x1, x1), b1p);
            acc2 = fma2(wi1p, pack2(x2, x2), b1p);
            acc3 = fma2(wi1p, pack2(x3, x3), b1p);
        }
#pragma unroll 2
        for (int k2 = 0; k2 < 26; ++k2) {
            ulonglong2 w = *(const ulonglong2*)&sW1[(k2*112 + gp) * 4];
            const u64* hr = &h1d[(k2*2)*16 + bbase];
            ulonglong2 pA = *(const ulonglong2*)hr;          // k even, b0,b1
            ulonglong2 pB = *(const ulonglong2*)(hr + 2);    // k even, b2,b3
            ulonglong2 pC = *(const ulonglong2*)(hr + 16);   // k odd,  b0,b1
            ulonglong2 pD = *(const ulonglong2*)(hr + 18);   // k odd,  b2,b3
            acc0 = fma2(w.x, pA.x, acc0);
            acc1 = fma2(w.x, pA.y, acc1);
            acc2 = fma2(w.x, pB.x, acc2);
            acc3 = fma2(w.x, pB.y, acc3);
            acc0 = fma2(w.y, pC.x, acc0);
            acc1 = fma2(w.y, pC.y, acc1);
            acc2 = fma2(w.y, pD.x, acc2);
            acc3 = fma2(w.y, pD.y, acc3);
        }
        {
            float v0, v1, u0, u1, w0, w1, z0, z1;
            unpack2(acc0, v0, v1); unpack2(acc1, u0, u1);
            unpack2(acc2, w0, w1); unpack2(acc3, z0, z1);
            float4 g0 = make_float4(actf(v0, c0, a0, d0), actf(u0, c0, a0, d0),
                                    actf(w0, c0, a0, d0), actf(z0, c0, a0, d0));
            float4 g1 = make_float4(actf(v1, C_SIG, 1.f, 0.f), actf(u1, C_SIG, 1.f, 0.f),
                                    actf(w1, C_SIG, 1.f, 0.f), actf(z1, C_SIG, 1.f, 0.f));
            *(float4*)&ag[agr0] = g0;
            *(float4*)&ag[agr1] = g1;
        }
        __syncthreads();

        // ======== Phase B: cell-1 state update ========
        {
            float iv = ag[jA*16 + bA];
            float fv = ag[896  + jA*16 + bA];
            float gv = ag[1792 + jA*16 + bA];
            float ov = ag[2688 + jA*16 + bA];
            float c = fv * c1a + iv * gv;
            c1a = c;
            float h = ov * tanh_c(c);
            h1d[jA*16 + bA] = pack2(h, h);
            if (vB) {
                iv = ag[jB*16 + bB];
                fv = ag[896  + jB*16 + bB];
                gv = ag[1792 + jB*16 + bB];
                ov = ag[2688 + jB*16 + bB];
                c = fv * c1b + iv * gv;
                c1b = c;
                h = ov * tanh_c(c);
                h1d[jB*16 + bB] = pack2(h, h);
            }
        }
        __syncthreads();

        // ======== Phase C: cell-2 gates ========
        acc0 = b2p; acc1 = b2p; acc2 = b2p; acc3 = b2p;
#pragma unroll 3
        for (int k = 0; k < HH; ++k) {
            ulonglong2 w = *(const ulonglong2*)&sWC[(k*112 + gp) * 4];  // (Wih2 pair, Whh2 pair)
            const u64* h1r = &h1d[k*16 + bbase];
            const u64* h2r = &h2d[k*16 + bbase];
            ulonglong2 p  = *(const ulonglong2*)h1r;
            ulonglong2 p2 = *(const ulonglong2*)(h1r + 2);
            ulonglong2 r  = *(const ulonglong2*)h2r;
            ulonglong2 r2 = *(const ulonglong2*)(h2r + 2);
            acc0 = fma2(w.x, p.x,  acc0);
            acc1 = fma2(w.x, p.y,  acc1);
            acc2 = fma2(w.x, p2.x, acc2);
            acc3 = fma2(w.x, p2.y, acc3);
            acc0 = fma2(w.y, r.x,  acc0);
            acc1 = fma2(w.y, r.y,  acc1);
            acc2 = fma2(w.y, r2.x, acc2);
            acc3 = fma2(w.y, r2.y, acc3);
        }
        {
            float v0, v1, u0, u1, w0, w1, z0, z1;
            unpack2(acc0, v0, v1); unpack2(acc1, u0, u1);
            unpack2(acc2, w0, w1); unpack2(acc3, z0, z1);
            float4 g0 = make_float4(actf(v0, c0, a0, d0), actf(u0, c0, a0, d0),
                                    actf(w0, c0, a0, d0), actf(z0, c0, a0, d0));
            float4 g1 = make_float4(actf(v1, C_SIG, 1.f, 0.f), actf(u1, C_SIG, 1.f, 0.f),
                                    actf(w1, C_SIG, 1.f, 0.f), actf(z1, C_SIG, 1.f, 0.f));
            *(float4*)&ag[agr0] = g0;
            *(float4*)&ag[agr1] = g1;
        }
        __syncthreads();

        // ======== Phase D: cell-2 state update ========
        {
            float iv = ag[jA*16 + bA];
            float fv = ag[896  + jA*16 + bA];
            float gv = ag[1792 + jA*16 + bA];
            float ov = ag[2688 + jA*16 + bA];
            float c = fv * c2a + iv * gv;
            c2a = c;
            float h = ov * tanh_c(c);
            h2d[jA*16 + bA] = pack2(h, h);
            if (vB) {
                iv = ag[jB*16 + bB];
                fv = ag[896  + jB*16 + bB];
                gv = ag[1792 + jB*16 + bB];
                ov = ag[2688 + jB*16 + bB];
                c = fv * c2b + iv * gv;
                c2b = c;
                h = ov * tanh_c(c);
                h2d[jB*16 + bB] = pack2(h, h);
            }
        }
        __syncthreads();

        // ======== Phase E: fc head (64 threads, 4-lane split-K) ========
        if (tid < 64) {
            int b = tid >> 2, q = tid & 3;
            float a = 0.f;
            for (int k = q; k < HH; k += 4)
                a += *(const float*)&h2d[k*16 + b] * sfcw[k];   // low lane of (h,h)
            a += __shfl_xor_sync(0xFFFFFFFFu, a, 1);
            a += __shfl_xor_sync(0xFFFFFFFFu, a, 2);
            if (q == 0) out[(size_t)(b0 + b) * TT + t] = a + fcb;
        }
        // h2d rewritten only in Phase D(t+1), 3 barriers away; xs rewritten behind
        // the staging barrier. Safe.
    }
}

extern "C" void kernel_launch(void* const* d_in, const int* in_sizes, int n_in,
                              void* d_out, int out_size)
{
    const float* x    = (const float*)d_in[0];
    // d_in[1] = future (0) — ignored
    const float* Wih1 = (const float*)d_in[2];
    const float* bih1 = (const float*)d_in[3];
    const float* Whh1 = (const float*)d_in[4];
    const float* bhh1 = (const float*)d_in[5];
    const float* Wih2 = (const float*)d_in[6];
    const float* bih2 = (const float*)d_in[7];
    const float* Whh2 = (const float*)d_in[8];
    const float* bhh2 = (const float*)d_in[9];
    const float* fcw  = (const float*)d_in[10];
    const float* fcb  = (const float*)d_in[11];
    float* out = (float*)d_out;

    const size_t smem = SMEM_FLOATS * sizeof(float);   // ~169 KB
    cudaFuncSetAttribute(lstm2_persistent_kernel,
                         cudaFuncAttributeMaxDynamicSharedMemorySize, (int)smem);

    lstm2_persistent_kernel<<<BB / BT, NT, smem>>>(
        x, Wih1, bih1, Whh1, bhh1, Wih2, bih2, Whh2, bhh2, fcw, fcb, out);
}

// round 6
// speedup vs baseline: 1.9393x; 1.9393x over previous
#include <cuda_runtime.h>
#include <cstddef>

#define HH 51
#define GG 204
#define BT 16
#define NT 224
#define TT 512
#define BB 2048
#define AGP 20      // padded ag row stride (floats): conflict-free STS.128
#define TCH 64

typedef unsigned long long u64;

__device__ __forceinline__ u64 pack2(float lo, float hi) {
    u64 r; asm("mov.b64 %0, {%1,%2};" : "=l"(r) : "f"(lo), "f"(hi)); return r;
}
__device__ __forceinline__ void unpack2(u64 v, float& lo, float& hi) {
    asm("mov.b64 {%0,%1}, %2;" : "=f"(lo), "=f"(hi) : "l"(v));
}
__device__ __forceinline__ u64 fma2(u64 a, u64 b, u64 c) {
    u64 d; asm("fma.rn.f32x2 %0, %1, %2, %3;" : "=l"(d) : "l"(a), "l"(b), "l"(c)); return d;
}
// act(v) = a * rcp(1 + ex2(c*v)) + d
__device__ __forceinline__ float actf(float v, float c, float a, float d) {
    float e; asm("ex2.approx.ftz.f32 %0, %1;" : "=f"(e) : "f"(v * c));
    float r; asm("rcp.approx.ftz.f32 %0, %1;" : "=f"(r) : "f"(1.f + e));
    return fmaf(a, r, d);
}
#define C_SIG (-1.442695041f)
#define C_TNH ( 2.885390082f)
__device__ __forceinline__ float tanh_c(float v) { return actf(v, C_TNH, -2.f, 1.f); }

__global__ void __launch_bounds__(NT, 1) lstm2_regw_kernel(
    const float* __restrict__ x,
    const float* __restrict__ Wih1, const float* __restrict__ bih1,
    const float* __restrict__ Whh1, const float* __restrict__ bhh1,
    const float* __restrict__ Wih2, const float* __restrict__ bih2,
    const float* __restrict__ Whh2, const float* __restrict__ bhh2,
    const float* __restrict__ fcwg, const float* __restrict__ fcbg,
    float* __restrict__ out)
{
    __shared__ __align__(16) float h1[HH*BT];     // [k][b]
    __shared__ __align__(16) float h2[HH*BT];
    __shared__ __align__(16) float ag[GG*AGP];    // [gate][20pad] activated gates
    __shared__ __align__(16) float xs2[TCH*BT];   // [tc][b]
    __shared__ float sfcw[HH];

    const int tid = threadIdx.x;
    const int b0  = blockIdx.x * BT;

    const bool valid = (tid < GG);
    const int gs  = valid ? tid : (GG - 1);
    const int cls = gs / HH;                       // 0:i 1:f 2:g 3:o

    // ---- weights into registers (one-time) ----
    float W1r[HH], Wi2r[HH], Wh2r[HH];
#pragma unroll
    for (int k = 0; k < HH; ++k) W1r[k]  = Whh1[gs*HH + k];
#pragma unroll
    for (int k = 0; k < HH; ++k) Wi2r[k] = Wih2[gs*HH + k];
#pragma unroll
    for (int k = 0; k < HH; ++k) Wh2r[k] = Whh2[gs*HH + k];

    const float b1 = bih1[gs] + bhh1[gs];
    const float b2 = bih2[gs] + bhh2[gs];
    const float w1x = Wih1[gs];
    const u64 b1d  = pack2(b1, b1);
    const u64 b2d  = pack2(b2, b2);
    const u64 wi1d = pack2(w1x, w1x);

    const float c0 = (cls == 2) ? C_TNH : C_SIG;
    const float a0 = (cls == 2) ? -2.f  : 1.f;
    const float d0 = (cls == 2) ?  1.f  : 0.f;

    // init shared state
    for (int i = tid; i < HH*BT; i += NT) { h1[i] = 0.f; h2[i] = 0.f; }
    if (tid < HH) sfcw[tid] = fcwg[tid];
    const float fcb = fcbg[0];

    float c1s[4] = {0.f, 0.f, 0.f, 0.f};
    float c2s[4] = {0.f, 0.f, 0.f, 0.f};

    __syncthreads();

    for (int t = 0; t < TT; ++t) {
        const int tc = t & (TCH - 1);
        if (tc == 0) {
            for (int i = tid; i < BT*TCH; i += NT) {
                int b = i >> 6, u = i & 63;
                xs2[(u << 4) + b] = x[(size_t)(b0 + b) * TT + t + u];
            }
            __syncthreads();
        }

        // ================= Phase A: cell-1 gates =================
        u64 acc[8];
        {
            const ulonglong2* xr = (const ulonglong2*)&xs2[tc << 4];
            ulonglong2 x01 = xr[0], x23 = xr[1], x45 = xr[2], x67 = xr[3];
            acc[0] = fma2(wi1d, x01.x, b1d);
            acc[1] = fma2(wi1d, x01.y, b1d);
            acc[2] = fma2(wi1d, x23.x, b1d);
            acc[3] = fma2(wi1d, x23.y, b1d);
            acc[4] = fma2(wi1d, x45.x, b1d);
            acc[5] = fma2(wi1d, x45.y, b1d);
            acc[6] = fma2(wi1d, x67.x, b1d);
            acc[7] = fma2(wi1d, x67.y, b1d);
        }
#pragma unroll
        for (int k = 0; k < HH; ++k) {
            u64 wd = pack2(W1r[k], W1r[k]);
            const ulonglong2* hr = (const ulonglong2*)&h1[k << 4];
            ulonglong2 p0 = hr[0], p1 = hr[1], p2 = hr[2], p3 = hr[3];
            acc[0] = fma2(wd, p0.x, acc[0]);
            acc[1] = fma2(wd, p0.y, acc[1]);
            acc[2] = fma2(wd, p1.x, acc[2]);
            acc[3] = fma2(wd, p1.y, acc[3]);
            acc[4] = fma2(wd, p2.x, acc[4]);
            acc[5] = fma2(wd, p2.y, acc[5]);
            acc[6] = fma2(wd, p3.x, acc[6]);
            acc[7] = fma2(wd, p3.y, acc[7]);
        }
        if (valid) {
            float r[16];
#pragma unroll
            for (int i = 0; i < 8; ++i) {
                float lo, hi; unpack2(acc[i], lo, hi);
                r[2*i]   = actf(lo, c0, a0, d0);
                r[2*i+1] = actf(hi, c0, a0, d0);
            }
            float* agr = &ag[gs * AGP];
#pragma unroll
            for (int q = 0; q < 4; ++q)
                *(float4*)&agr[q*4] = make_float4(r[4*q], r[4*q+1], r[4*q+2], r[4*q+3]);
        }
        __syncthreads();

        // ================= Phase B: cell-1 state update =================
#pragma unroll
        for (int s = 0; s < 4; ++s) {
            int idx = tid + s*NT;
            if (idx < HH*BT) {
                int j = idx >> 4, b = idx & 15;
                float iv = ag[( 0*HH + j)*AGP + b];
                float fv = ag[( 1*HH + j)*AGP + b];
                float gv = ag[( 2*HH + j)*AGP + b];
                float ov = ag[( 3*HH + j)*AGP + b];
                float c = fv * c1s[s] + iv * gv;
                c1s[s] = c;
                h1[(j << 4) + b] = ov * tanh_c(c);
            }
        }
        __syncthreads();

        // ================= Phase C: cell-2 gates =================
#pragma unroll
        for (int i = 0; i < 8; ++i) acc[i] = b2d;
#pragma unroll
        for (int k = 0; k < HH; ++k) {
            u64 wd1 = pack2(Wi2r[k], Wi2r[k]);
            u64 wd2 = pack2(Wh2r[k], Wh2r[k]);
            const ulonglong2* h1r = (const ulonglong2*)&h1[k << 4];
            const ulonglong2* h2r = (const ulonglong2*)&h2[k << 4];
            ulonglong2 p0 = h1r[0], p1 = h1r[1], p2 = h1r[2], p3 = h1r[3];
            ulonglong2 q0 = h2r[0], q1 = h2r[1], q2 = h2r[2], q3 = h2r[3];
            acc[0] = fma2(wd1, p0.x, acc[0]);
            acc[1] = fma2(wd1, p0.y, acc[1]);
            acc[2] = fma2(wd1, p1.x, acc[2]);
            acc[3] = fma2(wd1, p1.y, acc[3]);
            acc[4] = fma2(wd1, p2.x, acc[4]);
            acc[5] = fma2(wd1, p2.y, acc[5]);
            acc[6] = fma2(wd1, p3.x, acc[6]);
            acc[7] = fma2(wd1, p3.y, acc[7]);
            acc[0] = fma2(wd2, q0.x, acc[0]);
            acc[1] = fma2(wd2, q0.y, acc[1]);
            acc[2] = fma2(wd2, q1.x, acc[2]);
            acc[3] = fma2(wd2, q1.y, acc[3]);
            acc[4] = fma2(wd2, q2.x, acc[4]);
            acc[5] = fma2(wd2, q2.y, acc[5]);
            acc[6] = fma2(wd2, q3.x, acc[6]);
            acc[7] = fma2(wd2, q3.y, acc[7]);
        }
        if (valid) {
            float r[16];
#pragma unroll
            for (int i = 0; i < 8; ++i) {
                float lo, hi; unpack2(acc[i], lo, hi);
                r[2*i]   = actf(lo, c0, a0, d0);
                r[2*i+1] = actf(hi, c0, a0, d0);
            }
            float* agr = &ag[gs * AGP];
#pragma unroll
            for (int q = 0; q < 4; ++q)
                *(float4*)&agr[q*4] = make_float4(r[4*q], r[4*q+1], r[4*q+2], r[4*q+3]);
        }
        __syncthreads();

        // ================= Phase D: cell-2 state update =================
#pragma unroll
        for (int s = 0; s < 4; ++s) {
            int idx = tid + s*NT;
            if (idx < HH*BT) {
                int j = idx >> 4, b = idx & 15;
                float iv = ag[( 0*HH + j)*AGP + b];
                float fv = ag[( 1*HH + j)*AGP + b];
                float gv = ag[( 2*HH + j)*AGP + b];
                float ov = ag[( 3*HH + j)*AGP + b];
                float c = fv * c2s[s] + iv * gv;
                c2s[s] = c;
                h2[(j << 4) + b] = ov * tanh_c(c);
            }
        }
        __syncthreads();

        // ================= Phase E: fc head (64 threads, 4-way split-K) =====
        if (tid < 64) {
            int b = tid >> 2, q = tid & 3;
            float a = 0.f;
            for (int k = q; k < HH; k += 4)
                a += h2[(k << 4) + b] * sfcw[k];
            a += __shfl_xor_sync(0xFFFFFFFFu, a, 1);
            a += __shfl_xor_sync(0xFFFFFFFFu, a, 2);
            if (q == 0) out[(size_t)(b0 + b) * TT + t] = a + fcb;
        }
        // next writes to h2 are in Phase D(t+1), 3 barriers away — safe.
    }
}

extern "C" void kernel_launch(void* const* d_in, const int* in_sizes, int n_in,
                              void* d_out, int out_size)
{
    const float* x    = (const float*)d_in[0];
    // d_in[1] = future (0) — ignored
    const float* Wih1 = (const float*)d_in[2];
    const float* bih1 = (const float*)d_in[3];
    const float* Whh1 = (const float*)d_in[4];
    const float* bhh1 = (const float*)d_in[5];
    const float* Wih2 = (const float*)d_in[6];
    const float* bih2 = (const float*)d_in[7];
    const float* Whh2 = (const float*)d_in[8];
    const float* bhh2 = (const float*)d_in[9];
    const float* fcw  = (const float*)d_in[10];
    const float* fcb  = (const float*)d_in[11];
    float* out = (float*)d_out;

    lstm2_regw_kernel<<<BB / BT, NT>>>(
        x, Wih1, bih1, Whh1, bhh1, Wih2, bih2, Whh2, bhh2, fcw, fcb, out);
}